// round 1
// baseline (speedup 1.0000x reference)
#include <cuda_runtime.h>
#include <math.h>

#define NN 50000
#define EE 800000
#define DD 2048
#define CC 256
#define ESL (EE + NN)

// ---------------- scratch (static device globals; no runtime alloc) --------
__device__ float g_fA[NN * CC];   // h1_pre, later u
__device__ float g_fB[NN * CC];   // h1 (post-agg)
__device__ float g_fC[NN * CC];   // h2_pre, later v
__device__ float g_fD[NN * CC];   // h2 (post-agg)
__device__ float g_s[NN];
__device__ float g_t[NN];
__device__ int   g_deg[NN];
__device__ int   g_off[NN + 1];
__device__ int   g_cursor[NN];
__device__ int   g_csrc[ESL];

// ---------------- CSR build -------------------------------------------------
__global__ void init_deg_kernel(int* deg, int n) {
    int i = blockIdx.x * blockDim.x + threadIdx.x;
    if (i < n) deg[i] = 1;  // self loop
}

__global__ void count_kernel(const int* __restrict__ dst, int* deg, int E) {
    int i = blockIdx.x * blockDim.x + threadIdx.x;
    if (i < E) atomicAdd(&deg[dst[i]], 1);
}

__global__ void scan_kernel(const int* __restrict__ deg, int* __restrict__ off, int n) {
    __shared__ int sums[1024];
    int tid = threadIdx.x;
    int chunk = (n + 1023) / 1024;
    int beg = tid * chunk;
    int end = beg + chunk; if (end > n) end = n;
    int sum = 0;
    for (int i = beg; i < end; ++i) sum += deg[i];
    sums[tid] = sum;
    __syncthreads();
    // Hillis-Steele inclusive scan
    for (int o = 1; o < 1024; o <<= 1) {
        int v = (tid >= o) ? sums[tid - o] : 0;
        __syncthreads();
        sums[tid] += v;
        __syncthreads();
    }
    int base = (tid > 0) ? sums[tid - 1] : 0;
    for (int i = beg; i < end; ++i) { off[i] = base; base += deg[i]; }
    if (tid == 1023) off[n] = sums[1023];
}

__global__ void selfloop_kernel(const int* __restrict__ off, int* cursor, int* csrc, int n) {
    int i = blockIdx.x * blockDim.x + threadIdx.x;
    if (i < n) {
        int o = off[i];
        csrc[o] = i;           // self loop first (deterministic slot)
        cursor[i] = o + 1;
    }
}

__global__ void scatter_kernel(const int* __restrict__ src, const int* __restrict__ dst,
                               int* cursor, int* csrc, int E) {
    int i = blockIdx.x * blockDim.x + threadIdx.x;
    if (i < E) {
        int d = dst[i];
        int p = atomicAdd(&cursor[d], 1);
        csrc[p] = src[i];
    }
}

// ---------------- SGEMM: C[M,N] = A[M,K] @ B[K,N], row-major ----------------
#define BM 128
#define BN 128
#define BK 16
#define TM 8
#define TN 8

__global__ __launch_bounds__(256, 2)
void sgemm_kernel(const float* __restrict__ A, const float* __restrict__ B,
                  float* __restrict__ C, int M, int N, int K)
{
    __shared__ float As[BK][BM];
    __shared__ float Bs[BK][BN];

    const int tid = threadIdx.x;
    const int brow = blockIdx.x * BM;
    const int bcol = blockIdx.y * BN;

    // A tile loads: 128x16 floats = 512 float4 / 256 threads = 2 each
    const int aRow0 = (tid      ) >> 2, aCol0 = ((tid      ) & 3) * 4;
    const int aRow1 = (tid + 256) >> 2, aCol1 = ((tid + 256) & 3) * 4;
    // B tile loads: 16x128 floats = 512 float4 / 256 threads = 2 each
    const int bRow0 = (tid      ) >> 5, bCol0 = ((tid      ) & 31) * 4;
    const int bRow1 = (tid + 256) >> 5, bCol1 = ((tid + 256) & 31) * 4;

    const int tm = (tid >> 4) * TM;
    const int tn = (tid & 15) * TN;

    float acc[TM][TN];
    #pragma unroll
    for (int i = 0; i < TM; i++)
        #pragma unroll
        for (int j = 0; j < TN; j++) acc[i][j] = 0.f;

    const float* Aptr = A + (size_t)brow * K;
    const float* Bptr = B + bcol;
    const int numTiles = K / BK;

    float4 pa0, pa1, pb0, pb1;

    // prologue load tile 0
    {
        int k0 = 0;
        pa0 = (brow + aRow0 < M) ? *(const float4*)(Aptr + (size_t)aRow0 * K + k0 + aCol0) : make_float4(0,0,0,0);
        pa1 = (brow + aRow1 < M) ? *(const float4*)(Aptr + (size_t)aRow1 * K + k0 + aCol1) : make_float4(0,0,0,0);
        pb0 = *(const float4*)(Bptr + (size_t)(k0 + bRow0) * N + bCol0);
        pb1 = *(const float4*)(Bptr + (size_t)(k0 + bRow1) * N + bCol1);
    }
    // store to smem
    As[aCol0 + 0][aRow0] = pa0.x; As[aCol0 + 1][aRow0] = pa0.y;
    As[aCol0 + 2][aRow0] = pa0.z; As[aCol0 + 3][aRow0] = pa0.w;
    As[aCol1 + 0][aRow1] = pa1.x; As[aCol1 + 1][aRow1] = pa1.y;
    As[aCol1 + 2][aRow1] = pa1.z; As[aCol1 + 3][aRow1] = pa1.w;
    *(float4*)(&Bs[bRow0][bCol0]) = pb0;
    *(float4*)(&Bs[bRow1][bCol1]) = pb1;
    __syncthreads();

    for (int t = 1; t < numTiles; ++t) {
        // prefetch next tile to registers
        int k0 = t * BK;
        pa0 = (brow + aRow0 < M) ? *(const float4*)(Aptr + (size_t)aRow0 * K + k0 + aCol0) : make_float4(0,0,0,0);
        pa1 = (brow + aRow1 < M) ? *(const float4*)(Aptr + (size_t)aRow1 * K + k0 + aCol1) : make_float4(0,0,0,0);
        pb0 = *(const float4*)(Bptr + (size_t)(k0 + bRow0) * N + bCol0);
        pb1 = *(const float4*)(Bptr + (size_t)(k0 + bRow1) * N + bCol1);

        // compute current tile
        #pragma unroll
        for (int kk = 0; kk < BK; ++kk) {
            float a[TM], b[TN];
            #pragma unroll
            for (int i = 0; i < TM; i++) a[i] = As[kk][tm + i];
            #pragma unroll
            for (int j = 0; j < TN; j++) b[j] = Bs[kk][tn + j];
            #pragma unroll
            for (int i = 0; i < TM; i++)
                #pragma unroll
                for (int j = 0; j < TN; j++) acc[i][j] += a[i] * b[j];
        }
        __syncthreads();
        As[aCol0 + 0][aRow0] = pa0.x; As[aCol0 + 1][aRow0] = pa0.y;
        As[aCol0 + 2][aRow0] = pa0.z; As[aCol0 + 3][aRow0] = pa0.w;
        As[aCol1 + 0][aRow1] = pa1.x; As[aCol1 + 1][aRow1] = pa1.y;
        As[aCol1 + 2][aRow1] = pa1.z; As[aCol1 + 3][aRow1] = pa1.w;
        *(float4*)(&Bs[bRow0][bCol0]) = pb0;
        *(float4*)(&Bs[bRow1][bCol1]) = pb1;
        __syncthreads();
    }
    // last tile compute
    #pragma unroll
    for (int kk = 0; kk < BK; ++kk) {
        float a[TM], b[TN];
        #pragma unroll
        for (int i = 0; i < TM; i++) a[i] = As[kk][tm + i];
        #pragma unroll
        for (int j = 0; j < TN; j++) b[j] = Bs[kk][tn + j];
        #pragma unroll
        for (int i = 0; i < TM; i++)
            #pragma unroll
            for (int j = 0; j < TN; j++) acc[i][j] += a[i] * b[j];
    }

    #pragma unroll
    for (int i = 0; i < TM; i++) {
        int grow = brow + tm + i;
        if (grow < M) {
            float4 o0 = make_float4(acc[i][0], acc[i][1], acc[i][2], acc[i][3]);
            float4 o1 = make_float4(acc[i][4], acc[i][5], acc[i][6], acc[i][7]);
            *(float4*)(&C[(size_t)grow * N + bcol + tn    ]) = o0;
            *(float4*)(&C[(size_t)grow * N + bcol + tn + 4]) = o1;
        }
    }
}

// ---------------- per-node attention scalars: s = h.a_src, t = h.a_dst ------
__global__ void node_dots_kernel(const float* __restrict__ h,
                                 const float* __restrict__ a_src,
                                 const float* __restrict__ a_dst,
                                 float* __restrict__ s, float* __restrict__ t, int n)
{
    int node = (blockIdx.x * blockDim.x + threadIdx.x) >> 5;
    if (node >= n) return;
    int lane = threadIdx.x & 31;
    const float4* hp  = (const float4*)(h + (size_t)node * CC);
    const float4* as4 = (const float4*)a_src;
    const float4* ad4 = (const float4*)a_dst;
    float ss = 0.f, tt = 0.f;
    #pragma unroll
    for (int j = 0; j < 2; j++) {
        int idx = lane + 32 * j;
        float4 hv = hp[idx];
        float4 av = as4[idx];
        float4 dv = ad4[idx];
        ss += hv.x * av.x + hv.y * av.y + hv.z * av.z + hv.w * av.w;
        tt += hv.x * dv.x + hv.y * dv.y + hv.z * dv.z + hv.w * dv.w;
    }
    #pragma unroll
    for (int o = 16; o > 0; o >>= 1) {
        ss += __shfl_down_sync(0xffffffffu, ss, o);
        tt += __shfl_down_sync(0xffffffffu, tt, o);
    }
    if (lane == 0) { s[node] = ss; t[node] = tt; }
}

// ---------------- warp-per-node online-softmax aggregation ------------------
__global__ void gat_agg_kernel(const float* __restrict__ h,
                               const float* __restrict__ s,
                               const float* __restrict__ t,
                               const int* __restrict__ off,
                               const int* __restrict__ csrc,
                               const float* __restrict__ bias,
                               float* __restrict__ out, int n)
{
    int node = (blockIdx.x * blockDim.x + threadIdx.x) >> 5;
    if (node >= n) return;
    int lane = threadIdx.x & 31;
    float tv = t[node];
    int beg = off[node], end = off[node + 1];
    float m = -1e30f, d = 0.f;
    float4 acc0 = make_float4(0,0,0,0), acc1 = make_float4(0,0,0,0);
    for (int p = beg; p < end; ++p) {
        int src = csrc[p];
        float e = s[src] + tv;
        e = (e > 0.f) ? e : 0.2f * e;          // leaky relu
        float mn = fmaxf(m, e);
        float sc = __expf(m - mn);
        float w  = __expf(e - mn);
        d = d * sc + w;
        const float4* hp = (const float4*)(h + (size_t)src * CC);
        float4 v0 = hp[lane], v1 = hp[lane + 32];
        acc0.x = acc0.x * sc + w * v0.x;  acc0.y = acc0.y * sc + w * v0.y;
        acc0.z = acc0.z * sc + w * v0.z;  acc0.w = acc0.w * sc + w * v0.w;
        acc1.x = acc1.x * sc + w * v1.x;  acc1.y = acc1.y * sc + w * v1.y;
        acc1.z = acc1.z * sc + w * v1.z;  acc1.w = acc1.w * sc + w * v1.w;
        m = mn;
    }
    float inv = 1.f / (d + 1e-16f);
    const float4* b4 = (const float4*)bias;
    float4 bb0 = b4[lane], bb1 = b4[lane + 32];
    float4 o0, o1;
    o0.x = acc0.x * inv + bb0.x;  o0.y = acc0.y * inv + bb0.y;
    o0.z = acc0.z * inv + bb0.z;  o0.w = acc0.w * inv + bb0.w;
    o1.x = acc1.x * inv + bb1.x;  o1.y = acc1.y * inv + bb1.y;
    o1.z = acc1.z * inv + bb1.z;  o1.w = acc1.w * inv + bb1.w;
    float4* op = (float4*)(out + (size_t)node * CC);
    op[lane] = o0;
    op[lane + 32] = o1;
}

// ---------------- edge predictor (factorized) -------------------------------
__global__ void edge_pred_kernel(const float* __restrict__ u, const float* __restrict__ v,
                                 const int* __restrict__ esrc, const int* __restrict__ edst,
                                 const float* __restrict__ bp1, const float* __restrict__ wp2,
                                 const float* __restrict__ bp2, float* __restrict__ out, int E)
{
    int e = (blockIdx.x * blockDim.x + threadIdx.x) >> 5;
    if (e >= E) return;
    int lane = threadIdx.x & 31;
    int sI = esrc[e], dI = edst[e];
    const float4* up = (const float4*)(u + (size_t)sI * CC);
    const float4* vp = (const float4*)(v + (size_t)dI * CC);
    const float4* b4 = (const float4*)bp1;
    const float4* w4 = (const float4*)wp2;
    float sum = 0.f;
    #pragma unroll
    for (int j = 0; j < 2; j++) {
        int idx = lane + 32 * j;
        float4 a = up[idx], b = vp[idx], c = b4[idx], w = w4[idx];
        float r;
        r = a.x + b.x + c.x; r = fmaxf(r, 0.f); sum += r * w.x;
        r = a.y + b.y + c.y; r = fmaxf(r, 0.f); sum += r * w.y;
        r = a.z + b.z + c.z; r = fmaxf(r, 0.f); sum += r * w.z;
        r = a.w + b.w + c.w; r = fmaxf(r, 0.f); sum += r * w.w;
    }
    #pragma unroll
    for (int o = 16; o > 0; o >>= 1) sum += __shfl_down_sync(0xffffffffu, sum, o);
    if (lane == 0) out[e] = sum + bp2[0];
}

// ---------------- host driver -----------------------------------------------
extern "C" void kernel_launch(void* const* d_in, const int* in_sizes, int n_in,
                              void* d_out, int out_size)
{
    const float* x      = (const float*)d_in[0];
    const int*   ei     = (const int*)  d_in[1];
    const float* W1     = (const float*)d_in[2];
    const float* a_src1 = (const float*)d_in[3];
    const float* a_dst1 = (const float*)d_in[4];
    const float* b1     = (const float*)d_in[5];
    const float* W2     = (const float*)d_in[6];
    const float* a_src2 = (const float*)d_in[7];
    const float* a_dst2 = (const float*)d_in[8];
    const float* b2     = (const float*)d_in[9];
    const float* Wp1    = (const float*)d_in[10];
    const float* bp1    = (const float*)d_in[11];
    const float* wp2    = (const float*)d_in[12];
    const float* bp2    = (const float*)d_in[13];
    float* out          = (float*)d_out;

    const int* esrc = ei;
    const int* edst = ei + EE;

    float *fA, *fB, *fC, *fD, *s, *t;
    int *deg, *off, *cursor, *csrc;
    cudaGetSymbolAddress((void**)&fA, g_fA);
    cudaGetSymbolAddress((void**)&fB, g_fB);
    cudaGetSymbolAddress((void**)&fC, g_fC);
    cudaGetSymbolAddress((void**)&fD, g_fD);
    cudaGetSymbolAddress((void**)&s,  g_s);
    cudaGetSymbolAddress((void**)&t,  g_t);
    cudaGetSymbolAddress((void**)&deg, g_deg);
    cudaGetSymbolAddress((void**)&off, g_off);
    cudaGetSymbolAddress((void**)&cursor, g_cursor);
    cudaGetSymbolAddress((void**)&csrc, g_csrc);

    const int TPB = 256;
    dim3 gN((NN + TPB - 1) / TPB);
    dim3 gE((EE + TPB - 1) / TPB);
    dim3 gWarpN((NN * 32 + TPB - 1) / TPB);
    dim3 gWarpE((EE * 32 + TPB - 1) / TPB);

    // ---- CSR build (dst-major, self loops first) ----
    init_deg_kernel<<<gN, TPB>>>(deg, NN);
    count_kernel<<<gE, TPB>>>(edst, deg, EE);
    scan_kernel<<<1, 1024>>>(deg, off, NN);
    selfloop_kernel<<<gN, TPB>>>(off, cursor, csrc, NN);
    scatter_kernel<<<gE, TPB>>>(esrc, edst, cursor, csrc, EE);

    // ---- layer 1 ----
    dim3 grid1((NN + BM - 1) / BM, CC / BN);
    sgemm_kernel<<<grid1, 256>>>(x, W1, fA, NN, CC, DD);           // h1_pre
    node_dots_kernel<<<gWarpN, TPB>>>(fA, a_src1, a_dst1, s, t, NN);
    gat_agg_kernel<<<gWarpN, TPB>>>(fA, s, t, off, csrc, b1, fB, NN);  // h1

    // ---- layer 2 ----
    sgemm_kernel<<<grid1, 256>>>(fB, W2, fC, NN, CC, CC);          // h2_pre
    node_dots_kernel<<<gWarpN, TPB>>>(fC, a_src2, a_dst2, s, t, NN);
    gat_agg_kernel<<<gWarpN, TPB>>>(fC, s, t, off, csrc, b2, fD, NN);  // h2

    // ---- edge predictor: u = h2 @ Wp1_top, v = h2 @ Wp1_bot ----
    sgemm_kernel<<<grid1, 256>>>(fD, Wp1,           fA, NN, CC, CC);   // u
    sgemm_kernel<<<grid1, 256>>>(fD, Wp1 + CC * CC, fC, NN, CC, CC);   // v
    edge_pred_kernel<<<gWarpE, TPB>>>(fA, fC, esrc, edst, bp1, wp2, bp2, out, EE);
}

// round 3
// speedup vs baseline: 1.4908x; 1.4908x over previous
#include <cuda_runtime.h>
#include <cuda_bf16.h>
#include <math.h>
#include <stdint.h>

#define NN 50000
#define EE 800000
#define DD 2048
#define CC 256
#define ESL (EE + NN)

// ---------------- scratch (static device globals; no runtime alloc) --------
__device__ float g_fA[NN * CC];    // h1_pre
__device__ float g_fB[NN * CC];    // h1
__device__ float g_fC[NN * CC];    // h2_pre
__device__ float g_fD[NN * CC];    // h2
__device__ float g_uv[NN * 512];   // [u | v] per node
__device__ __nv_bfloat16 g_Bh[512 * 2048];  // packed B hi (max size: W1)
__device__ __nv_bfloat16 g_Bl[512 * 2048];  // packed B lo
__device__ float g_s[NN];
__device__ float g_t[NN];
__device__ int   g_deg[NN];
__device__ int   g_off[NN + 1];
__device__ int   g_cursor[NN];
__device__ int   g_csrc[ESL];

// ================= helpers ==================================================
__device__ __forceinline__ uint32_t smem_u32(const void* p) {
    uint32_t a;
    asm("{ .reg .u64 t; cvta.to.shared.u64 t, %1; cvt.u32.u64 %0, t; }"
        : "=r"(a) : "l"(p));
    return a;
}

#define LDSM4(r, addr) \
    asm volatile("ldmatrix.sync.aligned.m8n8.x4.shared.b16 {%0,%1,%2,%3}, [%4];" \
        : "=r"((r)[0]), "=r"((r)[1]), "=r"((r)[2]), "=r"((r)[3]) : "r"(addr))

#define MMA16816(c, a, b0, b1) \
    asm volatile("mma.sync.aligned.m16n8k16.row.col.f32.bf16.bf16.f32 " \
        "{%0,%1,%2,%3}, {%4,%5,%6,%7}, {%8,%9}, {%0,%1,%2,%3};" \
        : "+f"((c)[0]), "+f"((c)[1]), "+f"((c)[2]), "+f"((c)[3]) \
        : "r"((a)[0]), "r"((a)[1]), "r"((a)[2]), "r"((a)[3]), "r"(b0), "r"(b1))

// ---------------- CSR build -------------------------------------------------
__global__ void init_deg_kernel(int* deg, int n) {
    int i = blockIdx.x * blockDim.x + threadIdx.x;
    if (i < n) deg[i] = 1;
}

__global__ void count_kernel(const int* __restrict__ dst, int* deg, int E) {
    int i = blockIdx.x * blockDim.x + threadIdx.x;
    if (i < E) atomicAdd(&deg[dst[i]], 1);
}

__global__ void scan_kernel(const int* __restrict__ deg, int* __restrict__ off, int n) {
    __shared__ int sums[1024];
    int tid = threadIdx.x;
    int chunk = (n + 1023) / 1024;
    int beg = tid * chunk;
    int end = beg + chunk; if (end > n) end = n;
    int sum = 0;
    for (int i = beg; i < end; ++i) sum += deg[i];
    sums[tid] = sum;
    __syncthreads();
    for (int o = 1; o < 1024; o <<= 1) {
        int v = (tid >= o) ? sums[tid - o] : 0;
        __syncthreads();
        sums[tid] += v;
        __syncthreads();
    }
    int base = (tid > 0) ? sums[tid - 1] : 0;
    for (int i = beg; i < end; ++i) { off[i] = base; base += deg[i]; }
    if (tid == 1023) off[n] = sums[1023];
}

__global__ void selfloop_kernel(const int* __restrict__ off, int* cursor, int* csrc, int n) {
    int i = blockIdx.x * blockDim.x + threadIdx.x;
    if (i < n) {
        int o = off[i];
        csrc[o] = i;
        cursor[i] = o + 1;
    }
}

__global__ void scatter_kernel(const int* __restrict__ src, const int* __restrict__ dst,
                               int* cursor, int* csrc, int E) {
    int i = blockIdx.x * blockDim.x + threadIdx.x;
    if (i < E) {
        int d = dst[i];
        int p = atomicAdd(&cursor[d], 1);
        csrc[p] = src[i];
    }
}

// ---------------- B packing: W[K,N] fp32 -> Bh/Bl [N,K] bf16 (hi/lo split) --
__global__ void pack_b_kernel(const float* __restrict__ W,
                              __nv_bfloat16* __restrict__ Bh,
                              __nv_bfloat16* __restrict__ Bl, int K, int N) {
    int i = blockIdx.x * blockDim.x + threadIdx.x;
    if (i >= N * K) return;
    int n = i / K, k = i - n * K;
    float w = W[(size_t)k * N + n];
    __nv_bfloat16 h = __float2bfloat16(w);
    Bh[i] = h;
    Bl[i] = __float2bfloat16(w - __bfloat162float(h));
}

// ---------------- mma.sync split-bf16 GEMM ----------------------------------
// C[M,Nout](fp32) = A[M,Ktot](fp32) @ B ; D = Ah*Bh + Ah*Bl + Al*Bh
// Block tile 128x128, 8 warps of 64x32, BK=32, double-buffered smem.
#define GBM 128
#define GBN 128
#define GBK 32
#define LDAB 40                     // bf16 elems per smem row (32 + 8 pad)
#define STG_A (128 * LDAB * 2)      // 10240 bytes per matrix
#define STG_STAGE (4 * STG_A)       // Ah, Al, Bh, Bl

__global__ void __launch_bounds__(256, 1)
mma_gemm_kernel(const float* __restrict__ A,
                const __nv_bfloat16* __restrict__ Bhp,
                const __nv_bfloat16* __restrict__ Blp,
                float* __restrict__ C, int M, int Ktot, int Nout)
{
    extern __shared__ char sm[];
    const uint32_t sb = smem_u32(sm);

    const int tid  = threadIdx.x;
    const int wid  = tid >> 5;
    const int lane = tid & 31;
    const int brow = blockIdx.x * GBM;
    const int bcol = blockIdx.y * GBN;
    const int wm   = (wid & 1) * 64;
    const int wn   = (wid >> 1) * 32;

    float acc[4][4][4];
    #pragma unroll
    for (int i = 0; i < 4; i++)
        #pragma unroll
        for (int j = 0; j < 4; j++)
            #pragma unroll
            for (int r = 0; r < 4; r++) acc[i][j][r] = 0.f;

    const int T = Ktot / GBK;

    float4 pa[4];
    uint4  pbh[2], pbl[2];

    auto LOAD = [&](int t) {
        const int kt = t * GBK;
        #pragma unroll
        for (int it = 0; it < 4; ++it) {
            int idx = tid + it * 256;
            int r = idx >> 3, c4 = (idx & 7) * 4;
            pa[it] = (brow + r < M)
                ? *(const float4*)(A + (size_t)(brow + r) * Ktot + kt + c4)
                : make_float4(0.f, 0.f, 0.f, 0.f);
        }
        #pragma unroll
        for (int it = 0; it < 2; ++it) {
            int idx = tid + it * 256;
            int r = idx >> 2, c8 = (idx & 3) * 8;
            size_t g = (size_t)(bcol + r) * Ktot + kt + c8;
            pbh[it] = *(const uint4*)(Bhp + g);
            pbl[it] = *(const uint4*)(Blp + g);
        }
    };

    auto STORE = [&](int s) {
        char* st = sm + s * STG_STAGE;
        #pragma unroll
        for (int it = 0; it < 4; ++it) {
            int idx = tid + it * 256;
            int r = idx >> 3, c4 = (idx & 7) * 4;
            float4 v = pa[it];
            __nv_bfloat16 h0 = __float2bfloat16(v.x);
            __nv_bfloat16 h1 = __float2bfloat16(v.y);
            __nv_bfloat16 h2 = __float2bfloat16(v.z);
            __nv_bfloat16 h3 = __float2bfloat16(v.w);
            __nv_bfloat16 l0 = __float2bfloat16(v.x - __bfloat162float(h0));
            __nv_bfloat16 l1 = __float2bfloat16(v.y - __bfloat162float(h1));
            __nv_bfloat16 l2 = __float2bfloat16(v.z - __bfloat162float(h2));
            __nv_bfloat16 l3 = __float2bfloat16(v.w - __bfloat162float(h3));
            uint2 hp, lp;
            hp.x = ((uint32_t)__bfloat16_as_ushort(h1) << 16) | __bfloat16_as_ushort(h0);
            hp.y = ((uint32_t)__bfloat16_as_ushort(h3) << 16) | __bfloat16_as_ushort(h2);
            lp.x = ((uint32_t)__bfloat16_as_ushort(l1) << 16) | __bfloat16_as_ushort(l0);
            lp.y = ((uint32_t)__bfloat16_as_ushort(l3) << 16) | __bfloat16_as_ushort(l2);
            uint32_t off = (uint32_t)(r * LDAB + c4) * 2;
            *(uint2*)(st + off)         = hp;
            *(uint2*)(st + STG_A + off) = lp;
        }
        #pragma unroll
        for (int it = 0; it < 2; ++it) {
            int idx = tid + it * 256;
            int r = idx >> 2, c8 = (idx & 3) * 8;
            uint32_t off = (uint32_t)(r * LDAB + c8) * 2;
            *(uint4*)(st + 2 * STG_A + off) = pbh[it];
            *(uint4*)(st + 3 * STG_A + off) = pbl[it];
        }
    };

    const int lrow = lane & 15;          // ldmatrix row within 16
    const int lcol = (lane >> 4) & 1;    // k-half select

    auto COMPUTE = [&](int s) {
        const uint32_t base = sb + s * STG_STAGE;
        #pragma unroll
        for (int ks = 0; ks < 2; ++ks) {
            const uint32_t coff = (uint32_t)(ks * 16 + lcol * 8) * 2;
            uint32_t ah[4][4], al[4][4], bh[2][4], bl[2][4];
            #pragma unroll
            for (int i = 0; i < 4; ++i) {
                uint32_t addr = base + (uint32_t)((wm + i * 16 + lrow) * LDAB) * 2 + coff;
                LDSM4(ah[i], addr);
                LDSM4(al[i], addr + STG_A);
            }
            #pragma unroll
            for (int g = 0; g < 2; ++g) {
                uint32_t addr = base + 2 * STG_A
                              + (uint32_t)((wn + g * 16 + lrow) * LDAB) * 2 + coff;
                LDSM4(bh[g], addr);
                LDSM4(bl[g], addr + STG_A);
            }
            #pragma unroll
            for (int i = 0; i < 4; ++i) {
                #pragma unroll
                for (int j = 0; j < 4; ++j) {
                    int g = j >> 1, sel = j & 1;
                    uint32_t b0h = bh[g][sel], b1h = bh[g][sel + 2];
                    uint32_t b0l = bl[g][sel], b1l = bl[g][sel + 2];
                    MMA16816(acc[i][j], ah[i], b0h, b1h);
                    MMA16816(acc[i][j], ah[i], b0l, b1l);
                    MMA16816(acc[i][j], al[i], b0h, b1h);
                }
            }
        }
    };

    LOAD(0);
    STORE(0);
    __syncthreads();

    for (int t = 1; t < T; ++t) {
        LOAD(t);
        COMPUTE((t - 1) & 1);
        __syncthreads();
        STORE(t & 1);
        __syncthreads();
    }
    COMPUTE((T - 1) & 1);

    // epilogue
    #pragma unroll
    for (int i = 0; i < 4; ++i) {
        int row0 = brow + wm + i * 16 + (lane >> 2);
        #pragma unroll
        for (int j = 0; j < 4; ++j) {
            int col = bcol + wn + j * 8 + (lane & 3) * 2;
            if (row0 < M) {
                float2 v = make_float2(acc[i][j][0], acc[i][j][1]);
                *(float2*)(C + (size_t)row0 * Nout + col) = v;
            }
            if (row0 + 8 < M) {
                float2 v = make_float2(acc[i][j][2], acc[i][j][3]);
                *(float2*)(C + (size_t)(row0 + 8) * Nout + col) = v;
            }
        }
    }
}

// ---------------- per-node attention scalars: s = h.a_src, t = h.a_dst ------
__global__ void node_dots_kernel(const float* __restrict__ h,
                                 const float* __restrict__ a_src,
                                 const float* __restrict__ a_dst,
                                 float* __restrict__ s, float* __restrict__ t, int n)
{
    int node = (blockIdx.x * blockDim.x + threadIdx.x) >> 5;
    if (node >= n) return;
    int lane = threadIdx.x & 31;
    const float4* hp  = (const float4*)(h + (size_t)node * CC);
    const float4* as4 = (const float4*)a_src;
    const float4* ad4 = (const float4*)a_dst;
    float ss = 0.f, tt = 0.f;
    #pragma unroll
    for (int j = 0; j < 2; j++) {
        int idx = lane + 32 * j;
        float4 hv = hp[idx];
        float4 av = as4[idx];
        float4 dv = ad4[idx];
        ss += hv.x * av.x + hv.y * av.y + hv.z * av.z + hv.w * av.w;
        tt += hv.x * dv.x + hv.y * dv.y + hv.z * dv.z + hv.w * dv.w;
    }
    #pragma unroll
    for (int o = 16; o > 0; o >>= 1) {
        ss += __shfl_down_sync(0xffffffffu, ss, o);
        tt += __shfl_down_sync(0xffffffffu, tt, o);
    }
    if (lane == 0) { s[node] = ss; t[node] = tt; }
}

// ---------------- warp-per-node online-softmax aggregation ------------------
__global__ void gat_agg_kernel(const float* __restrict__ h,
                               const float* __restrict__ s,
                               const float* __restrict__ t,
                               const int* __restrict__ off,
                               const int* __restrict__ csrc,
                               const float* __restrict__ bias,
                               float* __restrict__ out, int n)
{
    int node = (blockIdx.x * blockDim.x + threadIdx.x) >> 5;
    if (node >= n) return;
    int lane = threadIdx.x & 31;
    float tv = t[node];
    int beg = off[node], end = off[node + 1];
    float m = -1e30f, d = 0.f;
    float4 acc0 = make_float4(0,0,0,0), acc1 = make_float4(0,0,0,0);
    for (int p = beg; p < end; ++p) {
        int src = csrc[p];
        float e = s[src] + tv;
        e = (e > 0.f) ? e : 0.2f * e;
        float mn = fmaxf(m, e);
        float sc = __expf(m - mn);
        float w  = __expf(e - mn);
        d = d * sc + w;
        const float4* hp = (const float4*)(h + (size_t)src * CC);
        float4 v0 = hp[lane], v1 = hp[lane + 32];
        acc0.x = acc0.x * sc + w * v0.x;  acc0.y = acc0.y * sc + w * v0.y;
        acc0.z = acc0.z * sc + w * v0.z;  acc0.w = acc0.w * sc + w * v0.w;
        acc1.x = acc1.x * sc + w * v1.x;  acc1.y = acc1.y * sc + w * v1.y;
        acc1.z = acc1.z * sc + w * v1.z;  acc1.w = acc1.w * sc + w * v1.w;
        m = mn;
    }
    float inv = 1.f / (d + 1e-16f);
    const float4* b4 = (const float4*)bias;
    float4 bb0 = b4[lane], bb1 = b4[lane + 32];
    float4 o0, o1;
    o0.x = acc0.x * inv + bb0.x;  o0.y = acc0.y * inv + bb0.y;
    o0.z = acc0.z * inv + bb0.z;  o0.w = acc0.w * inv + bb0.w;
    o1.x = acc1.x * inv + bb1.x;  o1.y = acc1.y * inv + bb1.y;
    o1.z = acc1.z * inv + bb1.z;  o1.w = acc1.w * inv + bb1.w;
    float4* op = (float4*)(out + (size_t)node * CC);
    op[lane] = o0;
    op[lane + 32] = o1;
}

// ---------------- edge predictor (factorized, uv stride 512) ----------------
__global__ void edge_pred_kernel(const float* __restrict__ uv,
                                 const int* __restrict__ esrc, const int* __restrict__ edst,
                                 const float* __restrict__ bp1, const float* __restrict__ wp2,
                                 const float* __restrict__ bp2, float* __restrict__ out, int E)
{
    int e = (blockIdx.x * blockDim.x + threadIdx.x) >> 5;
    if (e >= E) return;
    int lane = threadIdx.x & 31;
    int sI = esrc[e], dI = edst[e];
    const float4* up = (const float4*)(uv + (size_t)sI * 512);
    const float4* vp = (const float4*)(uv + (size_t)dI * 512 + 256);
    const float4* b4 = (const float4*)bp1;
    const float4* w4 = (const float4*)wp2;
    float sum = 0.f;
    #pragma unroll
    for (int j = 0; j < 2; j++) {
        int idx = lane + 32 * j;
        float4 a = up[idx], b = vp[idx], c = b4[idx], w = w4[idx];
        float r;
        r = a.x + b.x + c.x; r = fmaxf(r, 0.f); sum += r * w.x;
        r = a.y + b.y + c.y; r = fmaxf(r, 0.f); sum += r * w.y;
        r = a.z + b.z + c.z; r = fmaxf(r, 0.f); sum += r * w.z;
        r = a.w + b.w + c.w; r = fmaxf(r, 0.f); sum += r * w.w;
    }
    #pragma unroll
    for (int o = 16; o > 0; o >>= 1) sum += __shfl_down_sync(0xffffffffu, sum, o);
    if (lane == 0) out[e] = sum + bp2[0];
}

// ---------------- host driver -----------------------------------------------
extern "C" void kernel_launch(void* const* d_in, const int* in_sizes, int n_in,
                              void* d_out, int out_size)
{
    const float* x      = (const float*)d_in[0];
    const int*   ei     = (const int*)  d_in[1];
    const float* W1     = (const float*)d_in[2];
    const float* a_src1 = (const float*)d_in[3];
    const float* a_dst1 = (const float*)d_in[4];
    const float* b1     = (const float*)d_in[5];
    const float* W2     = (const float*)d_in[6];
    const float* a_src2 = (const float*)d_in[7];
    const float* a_dst2 = (const float*)d_in[8];
    const float* b2     = (const float*)d_in[9];
    const float* Wp1    = (const float*)d_in[10];
    const float* bp1    = (const float*)d_in[11];
    const float* wp2    = (const float*)d_in[12];
    const float* bp2    = (const float*)d_in[13];
    float* out          = (float*)d_out;

    const int* esrc = ei;
    const int* edst = ei + EE;

    float *fA, *fB, *fC, *fD, *uv, *s, *t;
    __nv_bfloat16 *Bh, *Bl;
    int *deg, *off, *cursor, *csrc;
    cudaGetSymbolAddress((void**)&fA, g_fA);
    cudaGetSymbolAddress((void**)&fB, g_fB);
    cudaGetSymbolAddress((void**)&fC, g_fC);
    cudaGetSymbolAddress((void**)&fD, g_fD);
    cudaGetSymbolAddress((void**)&uv, g_uv);
    cudaGetSymbolAddress((void**)&Bh, g_Bh);
    cudaGetSymbolAddress((void**)&Bl, g_Bl);
    cudaGetSymbolAddress((void**)&s,  g_s);
    cudaGetSymbolAddress((void**)&t,  g_t);
    cudaGetSymbolAddress((void**)&deg, g_deg);
    cudaGetSymbolAddress((void**)&off, g_off);
    cudaGetSymbolAddress((void**)&cursor, g_cursor);
    cudaGetSymbolAddress((void**)&csrc, g_csrc);

    const int dynSmem = 2 * STG_STAGE;   // 81920 bytes
    cudaFuncSetAttribute(mma_gemm_kernel,
                         cudaFuncAttributeMaxDynamicSharedMemorySize, dynSmem);

    const int TPB = 256;
    dim3 gN((NN + TPB - 1) / TPB);
    dim3 gE((EE + TPB - 1) / TPB);
    dim3 gWarpN((NN * 32 + TPB - 1) / TPB);
    dim3 gWarpE((EE * 32 + TPB - 1) / TPB);
    const int MB = (NN + GBM - 1) / GBM;   // 391

    // ---- CSR build (dst-major, self loops first) ----
    init_deg_kernel<<<gN, TPB>>>(deg, NN);
    count_kernel<<<gE, TPB>>>(edst, deg, EE);
    scan_kernel<<<1, 1024>>>(deg, off, NN);
    selfloop_kernel<<<gN, TPB>>>(off, cursor, csrc, NN);
    scatter_kernel<<<gE, TPB>>>(esrc, edst, cursor, csrc, EE);

    // ---- layer 1: h1_pre = x @ W1 ----
    pack_b_kernel<<<(256 * 2048 + TPB - 1) / TPB, TPB>>>(W1, Bh, Bl, 2048, 256);
    mma_gemm_kernel<<<dim3(MB, 2), 256, dynSmem>>>(x, Bh, Bl, fA, NN, 2048, 256);
    node_dots_kernel<<<gWarpN, TPB>>>(fA, a_src1, a_dst1, s, t, NN);
    gat_agg_kernel<<<gWarpN, TPB>>>(fA, s, t, off, csrc, b1, fB, NN);

    // ---- layer 2: h2_pre = h1 @ W2 ----
    pack_b_kernel<<<(256 * 256 + TPB - 1) / TPB, TPB>>>(W2, Bh, Bl, 256, 256);
    mma_gemm_kernel<<<dim3(MB, 2), 256, dynSmem>>>(fB, Bh, Bl, fC, NN, 256, 256);
    node_dots_kernel<<<gWarpN, TPB>>>(fC, a_src2, a_dst2, s, t, NN);
    gat_agg_kernel<<<gWarpN, TPB>>>(fC, s, t, off, csrc, b2, fD, NN);

    // ---- edge predictor: [u | v] = h2 @ [Wp1_top | Wp1_bot] (N=512) ----
    pack_b_kernel<<<(256 * 256 + TPB - 1) / TPB, TPB>>>(Wp1, Bh, Bl, 256, 256);
    pack_b_kernel<<<(256 * 256 + TPB - 1) / TPB, TPB>>>(Wp1 + 256 * 256,
                                                        Bh + 256 * 256, Bl + 256 * 256,
                                                        256, 256);
    mma_gemm_kernel<<<dim3(MB, 4), 256, dynSmem>>>(fD, Bh, Bl, uv, NN, 256, 512);
    edge_pred_kernel<<<gWarpE, TPB>>>(uv, esrc, edst, bp1, wp2, bp2, out, EE);
}

// round 4
// speedup vs baseline: 1.7756x; 1.1910x over previous
#include <cuda_runtime.h>
#include <cuda_bf16.h>
#include <math.h>
#include <stdint.h>

#define NN 50000
#define EE 800000
#define DD 2048
#define CC 256
#define ESL (EE + NN)

// ---------------- scratch (static device globals; no runtime alloc) --------
__device__ float g_fA[NN * CC];    // h1_pre
__device__ float g_fB[NN * CC];    // h1
__device__ float g_fC[NN * CC];    // h2_pre
__device__ float g_fD[NN * CC];    // h2
__device__ float g_uv[NN * 512];   // [u | v] per node
__device__ __nv_bfloat16 g_Bh[512 * 2048];  // packed B hi (max size: W1)
__device__ __nv_bfloat16 g_Bl[512 * 2048];  // packed B lo
__device__ float g_s[NN];
__device__ float g_t[NN];
__device__ int   g_deg[NN];
__device__ int   g_off[NN + 1];
__device__ int   g_cursor[NN];
__device__ int   g_csrc[ESL];

// ================= helpers ==================================================
__device__ __forceinline__ uint32_t smem_u32(const void* p) {
    uint32_t a;
    asm("{ .reg .u64 t; cvta.to.shared.u64 t, %1; cvt.u32.u64 %0, t; }"
        : "=r"(a) : "l"(p));
    return a;
}

#define LDSM4(r, addr) \
    asm volatile("ldmatrix.sync.aligned.m8n8.x4.shared.b16 {%0,%1,%2,%3}, [%4];" \
        : "=r"((r)[0]), "=r"((r)[1]), "=r"((r)[2]), "=r"((r)[3]) : "r"(addr))

#define MMA16816(c, a, b0, b1) \
    asm volatile("mma.sync.aligned.m16n8k16.row.col.f32.bf16.bf16.f32 " \
        "{%0,%1,%2,%3}, {%4,%5,%6,%7}, {%8,%9}, {%0,%1,%2,%3};" \
        : "+f"((c)[0]), "+f"((c)[1]), "+f"((c)[2]), "+f"((c)[3]) \
        : "r"((a)[0]), "r"((a)[1]), "r"((a)[2]), "r"((a)[3]), "r"(b0), "r"(b1))

#define CP_ASYNC16(smem, gptr) \
    asm volatile("cp.async.cg.shared.global [%0], [%1], 16;" \
        :: "r"(smem), "l"(gptr) : "memory")
#define CP_COMMIT() asm volatile("cp.async.commit_group;" ::: "memory")
#define CP_WAIT0()  asm volatile("cp.async.wait_group 0;" ::: "memory")

// ---------------- CSR build -------------------------------------------------
__global__ void init_deg_kernel(int* deg, int n) {
    int i = blockIdx.x * blockDim.x + threadIdx.x;
    if (i < n) deg[i] = 1;
}

__global__ void count_kernel(const int* __restrict__ dst, int* deg, int E) {
    int i = blockIdx.x * blockDim.x + threadIdx.x;
    if (i < E) atomicAdd(&deg[dst[i]], 1);
}

__global__ void scan_kernel(const int* __restrict__ deg, int* __restrict__ off, int n) {
    __shared__ int sums[1024];
    int tid = threadIdx.x;
    int chunk = (n + 1023) / 1024;
    int beg = tid * chunk;
    int end = beg + chunk; if (end > n) end = n;
    int sum = 0;
    for (int i = beg; i < end; ++i) sum += deg[i];
    sums[tid] = sum;
    __syncthreads();
    for (int o = 1; o < 1024; o <<= 1) {
        int v = (tid >= o) ? sums[tid - o] : 0;
        __syncthreads();
        sums[tid] += v;
        __syncthreads();
    }
    int base = (tid > 0) ? sums[tid - 1] : 0;
    for (int i = beg; i < end; ++i) { off[i] = base; base += deg[i]; }
    if (tid == 1023) off[n] = sums[1023];
}

__global__ void selfloop_kernel(const int* __restrict__ off, int* cursor, int* csrc, int n) {
    int i = blockIdx.x * blockDim.x + threadIdx.x;
    if (i < n) {
        int o = off[i];
        csrc[o] = i;
        cursor[i] = o + 1;
    }
}

__global__ void scatter_kernel(const int* __restrict__ src, const int* __restrict__ dst,
                               int* cursor, int* csrc, int E) {
    int i = blockIdx.x * blockDim.x + threadIdx.x;
    if (i < E) {
        int d = dst[i];
        int p = atomicAdd(&cursor[d], 1);
        csrc[p] = src[i];
    }
}

// ---------------- B packing: W[K,N] fp32 -> Bh/Bl [N,K] bf16 (hi/lo split) --
__global__ void pack_b_kernel(const float* __restrict__ W,
                              __nv_bfloat16* __restrict__ Bh,
                              __nv_bfloat16* __restrict__ Bl, int K, int N) {
    int i = blockIdx.x * blockDim.x + threadIdx.x;
    if (i >= N * K) return;
    int n = i / K, k = i - n * K;
    float w = W[(size_t)k * N + n];
    __nv_bfloat16 h = __float2bfloat16(w);
    Bh[i] = h;
    Bl[i] = __float2bfloat16(w - __bfloat162float(h));
}

// ---------------- mma.sync split-bf16 GEMM ----------------------------------
// C[M,Nout](fp32) = A[M,Ktot](fp32) @ B ; D = Ah*Bh + Ah*Bl + Al*Bh
// 128x128 block, 8 warps of 64x32, BK=32, double buffer, 1 sync/stage,
// cp.async for B, 2 CTAs/SM.
#define GBM 128
#define GBN 128
#define GBK 32
#define LDAB 40                       // bf16 elems per smem row (32 + 8 pad)
#define MAT_BYTES (128 * LDAB * 2)    // 10240 per matrix
#define STG_STAGE (4 * MAT_BYTES)     // Ah, Al, Bh, Bl = 40960
#define AH_OFF 0
#define AL_OFF MAT_BYTES
#define BH_OFF (2 * MAT_BYTES)
#define BL_OFF (3 * MAT_BYTES)

__global__ void __launch_bounds__(256, 2)
mma_gemm_kernel(const float* __restrict__ A,
                const __nv_bfloat16* __restrict__ Bhp,
                const __nv_bfloat16* __restrict__ Blp,
                float* __restrict__ C, int M, int Ktot, int Nout)
{
    extern __shared__ char sm[];
    const uint32_t sb = smem_u32(sm);

    const int tid  = threadIdx.x;
    const int wid  = tid >> 5;
    const int lane = tid & 31;
    const int brow = blockIdx.x * GBM;
    const int bcol = blockIdx.y * GBN;
    const int wm   = (wid & 1) * 64;
    const int wn   = (wid >> 1) * 32;

    float acc[4][4][4];
    #pragma unroll
    for (int i = 0; i < 4; i++)
        #pragma unroll
        for (int j = 0; j < 4; j++)
            #pragma unroll
            for (int r = 0; r < 4; r++) acc[i][j][r] = 0.f;

    const int T = Ktot / GBK;

    // --- B via cp.async: 1024 16B chunks per stage (Bh then Bl), 4/thread ---
    auto ISSUE_B = [&](int t) {
        const int kt = t * GBK;
        const uint32_t stage = sb + (uint32_t)(t & 1) * STG_STAGE;
        #pragma unroll
        for (int it = 0; it < 4; ++it) {
            int idx = tid + it * 256;          // 0..1023
            int mat = idx >> 9;                // 0: Bh, 1: Bl
            int rr  = (idx >> 2) & 127;
            int cc  = idx & 3;                 // 16B chunk within row
            const __nv_bfloat16* src = mat ? Blp : Bhp;
            uint64_t g = __cvta_generic_to_global(
                src + (size_t)(bcol + rr) * Ktot + kt + cc * 8);
            uint32_t sa = stage + (uint32_t)(BH_OFF + mat * MAT_BYTES)
                        + (uint32_t)rr * (LDAB * 2) + (uint32_t)cc * 16;
            CP_ASYNC16(sa, g);
        }
        CP_COMMIT();
    };

    float4 pa[4];
    auto LOAD_A = [&](int t) {
        const int kt = t * GBK;
        #pragma unroll
        for (int it = 0; it < 4; ++it) {
            int idx = tid + it * 256;
            int r = idx >> 3, c4 = (idx & 7) * 4;
            pa[it] = (brow + r < M)
                ? *(const float4*)(A + (size_t)(brow + r) * Ktot + kt + c4)
                : make_float4(0.f, 0.f, 0.f, 0.f);
        }
    };

    auto STORE_A = [&](int t) {
        char* st = sm + (t & 1) * STG_STAGE;
        #pragma unroll
        for (int it = 0; it < 4; ++it) {
            int idx = tid + it * 256;
            int r = idx >> 3, c4 = (idx & 7) * 4;
            float4 v = pa[it];
            __nv_bfloat16 h0 = __float2bfloat16(v.x);
            __nv_bfloat16 h1 = __float2bfloat16(v.y);
            __nv_bfloat16 h2 = __float2bfloat16(v.z);
            __nv_bfloat16 h3 = __float2bfloat16(v.w);
            __nv_bfloat16 l0 = __float2bfloat16(v.x - __bfloat162float(h0));
            __nv_bfloat16 l1 = __float2bfloat16(v.y - __bfloat162float(h1));
            __nv_bfloat16 l2 = __float2bfloat16(v.z - __bfloat162float(h2));
            __nv_bfloat16 l3 = __float2bfloat16(v.w - __bfloat162float(h3));
            uint2 hp, lp;
            hp.x = ((uint32_t)__bfloat16_as_ushort(h1) << 16) | __bfloat16_as_ushort(h0);
            hp.y = ((uint32_t)__bfloat16_as_ushort(h3) << 16) | __bfloat16_as_ushort(h2);
            lp.x = ((uint32_t)__bfloat16_as_ushort(l1) << 16) | __bfloat16_as_ushort(l0);
            lp.y = ((uint32_t)__bfloat16_as_ushort(l3) << 16) | __bfloat16_as_ushort(l2);
            uint32_t off = (uint32_t)(r * LDAB + c4) * 2;
            *(uint2*)(st + AH_OFF + off) = hp;
            *(uint2*)(st + AL_OFF + off) = lp;
        }
    };

    const int lrow = lane & 15;
    const int lcol = (lane >> 4) & 1;

    auto COMPUTE = [&](int t) {
        const uint32_t base = sb + (uint32_t)(t & 1) * STG_STAGE;
        #pragma unroll
        for (int ks = 0; ks < 2; ++ks) {
            const uint32_t coff = (uint32_t)(ks * 16 + lcol * 8) * 2;
            uint32_t bh[2][4], bl[2][4];
            #pragma unroll
            for (int g = 0; g < 2; ++g) {
                uint32_t addr = base + (uint32_t)((wn + g * 16 + lrow) * LDAB) * 2 + coff;
                LDSM4(bh[g], addr + BH_OFF);
                LDSM4(bl[g], addr + BL_OFF);
            }
            #pragma unroll
            for (int i = 0; i < 4; ++i) {
                uint32_t aaddr = base + (uint32_t)((wm + i * 16 + lrow) * LDAB) * 2 + coff;
                uint32_t a[4];
                LDSM4(a, aaddr + AH_OFF);
                #pragma unroll
                for (int j = 0; j < 4; ++j) {
                    int g = j >> 1, sel = j & 1;
                    MMA16816(acc[i][j], a, bh[g][sel], bh[g][sel + 2]);
                }
                #pragma unroll
                for (int j = 0; j < 4; ++j) {
                    int g = j >> 1, sel = j & 1;
                    MMA16816(acc[i][j], a, bl[g][sel], bl[g][sel + 2]);
                }
                LDSM4(a, aaddr + AL_OFF);
                #pragma unroll
                for (int j = 0; j < 4; ++j) {
                    int g = j >> 1, sel = j & 1;
                    MMA16816(acc[i][j], a, bh[g][sel], bh[g][sel + 2]);
                }
            }
        }
    };

    // prologue: stage 0
    ISSUE_B(0);
    LOAD_A(0);
    STORE_A(0);
    CP_WAIT0();
    __syncthreads();

    for (int t = 0; t < T; ++t) {
        if (t + 1 < T) {
            ISSUE_B(t + 1);
            LOAD_A(t + 1);
        }
        COMPUTE(t);
        if (t + 1 < T) STORE_A(t + 1);
        CP_WAIT0();
        __syncthreads();
    }

    // epilogue
    #pragma unroll
    for (int i = 0; i < 4; ++i) {
        int row0 = brow + wm + i * 16 + (lane >> 2);
        #pragma unroll
        for (int j = 0; j < 4; ++j) {
            int col = bcol + wn + j * 8 + (lane & 3) * 2;
            if (row0 < M) {
                float2 v = make_float2(acc[i][j][0], acc[i][j][1]);
                *(float2*)(C + (size_t)row0 * Nout + col) = v;
            }
            if (row0 + 8 < M) {
                float2 v = make_float2(acc[i][j][2], acc[i][j][3]);
                *(float2*)(C + (size_t)(row0 + 8) * Nout + col) = v;
            }
        }
    }
}

// ---------------- per-node attention scalars: s = h.a_src, t = h.a_dst ------
__global__ void node_dots_kernel(const float* __restrict__ h,
                                 const float* __restrict__ a_src,
                                 const float* __restrict__ a_dst,
                                 float* __restrict__ s, float* __restrict__ t, int n)
{
    int node = (blockIdx.x * blockDim.x + threadIdx.x) >> 5;
    if (node >= n) return;
    int lane = threadIdx.x & 31;
    const float4* hp  = (const float4*)(h + (size_t)node * CC);
    const float4* as4 = (const float4*)a_src;
    const float4* ad4 = (const float4*)a_dst;
    float ss = 0.f, tt = 0.f;
    #pragma unroll
    for (int j = 0; j < 2; j++) {
        int idx = lane + 32 * j;
        float4 hv = hp[idx];
        float4 av = as4[idx];
        float4 dv = ad4[idx];
        ss += hv.x * av.x + hv.y * av.y + hv.z * av.z + hv.w * av.w;
        tt += hv.x * dv.x + hv.y * dv.y + hv.z * dv.z + hv.w * dv.w;
    }
    #pragma unroll
    for (int o = 16; o > 0; o >>= 1) {
        ss += __shfl_down_sync(0xffffffffu, ss, o);
        tt += __shfl_down_sync(0xffffffffu, tt, o);
    }
    if (lane == 0) { s[node] = ss; t[node] = tt; }
}

// ---------------- warp-per-node online-softmax aggregation ------------------
__global__ void gat_agg_kernel(const float* __restrict__ h,
                               const float* __restrict__ s,
                               const float* __restrict__ t,
                               const int* __restrict__ off,
                               const int* __restrict__ csrc,
                               const float* __restrict__ bias,
                               float* __restrict__ out, int n)
{
    int node = (blockIdx.x * blockDim.x + threadIdx.x) >> 5;
    if (node >= n) return;
    int lane = threadIdx.x & 31;
    float tv = t[node];
    int beg = off[node], end = off[node + 1];
    float m = -1e30f, d = 0.f;
    float4 acc0 = make_float4(0,0,0,0), acc1 = make_float4(0,0,0,0);
    for (int p = beg; p < end; ++p) {
        int src = csrc[p];
        float e = s[src] + tv;
        e = (e > 0.f) ? e : 0.2f * e;
        float mn = fmaxf(m, e);
        float sc = __expf(m - mn);
        float w  = __expf(e - mn);
        d = d * sc + w;
        const float4* hp = (const float4*)(h + (size_t)src * CC);
        float4 v0 = hp[lane], v1 = hp[lane + 32];
        acc0.x = acc0.x * sc + w * v0.x;  acc0.y = acc0.y * sc + w * v0.y;
        acc0.z = acc0.z * sc + w * v0.z;  acc0.w = acc0.w * sc + w * v0.w;
        acc1.x = acc1.x * sc + w * v1.x;  acc1.y = acc1.y * sc + w * v1.y;
        acc1.z = acc1.z * sc + w * v1.z;  acc1.w = acc1.w * sc + w * v1.w;
        m = mn;
    }
    float inv = 1.f / (d + 1e-16f);
    const float4* b4 = (const float4*)bias;
    float4 bb0 = b4[lane], bb1 = b4[lane + 32];
    float4 o0, o1;
    o0.x = acc0.x * inv + bb0.x;  o0.y = acc0.y * inv + bb0.y;
    o0.z = acc0.z * inv + bb0.z;  o0.w = acc0.w * inv + bb0.w;
    o1.x = acc1.x * inv + bb1.x;  o1.y = acc1.y * inv + bb1.y;
    o1.z = acc1.z * inv + bb1.z;  o1.w = acc1.w * inv + bb1.w;
    float4* op = (float4*)(out + (size_t)node * CC);
    op[lane] = o0;
    op[lane + 32] = o1;
}

// ---------------- edge predictor (factorized, uv stride 512) ----------------
__global__ void edge_pred_kernel(const float* __restrict__ uv,
                                 const int* __restrict__ esrc, const int* __restrict__ edst,
                                 const float* __restrict__ bp1, const float* __restrict__ wp2,
                                 const float* __restrict__ bp2, float* __restrict__ out, int E)
{
    int e = (blockIdx.x * blockDim.x + threadIdx.x) >> 5;
    if (e >= E) return;
    int lane = threadIdx.x & 31;
    int sI = esrc[e], dI = edst[e];
    const float4* up = (const float4*)(uv + (size_t)sI * 512);
    const float4* vp = (const float4*)(uv + (size_t)dI * 512 + 256);
    const float4* b4 = (const float4*)bp1;
    const float4* w4 = (const float4*)wp2;
    float sum = 0.f;
    #pragma unroll
    for (int j = 0; j < 2; j++) {
        int idx = lane + 32 * j;
        float4 a = up[idx], b = vp[idx], c = b4[idx], w = w4[idx];
        float r;
        r = a.x + b.x + c.x; r = fmaxf(r, 0.f); sum += r * w.x;
        r = a.y + b.y + c.y; r = fmaxf(r, 0.f); sum += r * w.y;
        r = a.z + b.z + c.z; r = fmaxf(r, 0.f); sum += r * w.z;
        r = a.w + b.w + c.w; r = fmaxf(r, 0.f); sum += r * w.w;
    }
    #pragma unroll
    for (int o = 16; o > 0; o >>= 1) sum += __shfl_down_sync(0xffffffffu, sum, o);
    if (lane == 0) out[e] = sum + bp2[0];
}

// ---------------- host driver -----------------------------------------------
extern "C" void kernel_launch(void* const* d_in, const int* in_sizes, int n_in,
                              void* d_out, int out_size)
{
    const float* x      = (const float*)d_in[0];
    const int*   ei     = (const int*)  d_in[1];
    const float* W1     = (const float*)d_in[2];
    const float* a_src1 = (const float*)d_in[3];
    const float* a_dst1 = (const float*)d_in[4];
    const float* b1     = (const float*)d_in[5];
    const float* W2     = (const float*)d_in[6];
    const float* a_src2 = (const float*)d_in[7];
    const float* a_dst2 = (const float*)d_in[8];
    const float* b2     = (const float*)d_in[9];
    const float* Wp1    = (const float*)d_in[10];
    const float* bp1    = (const float*)d_in[11];
    const float* wp2    = (const float*)d_in[12];
    const float* bp2    = (const float*)d_in[13];
    float* out          = (float*)d_out;

    const int* esrc = ei;
    const int* edst = ei + EE;

    float *fA, *fB, *fC, *fD, *uv, *s, *t;
    __nv_bfloat16 *Bh, *Bl;
    int *deg, *off, *cursor, *csrc;
    cudaGetSymbolAddress((void**)&fA, g_fA);
    cudaGetSymbolAddress((void**)&fB, g_fB);
    cudaGetSymbolAddress((void**)&fC, g_fC);
    cudaGetSymbolAddress((void**)&fD, g_fD);
    cudaGetSymbolAddress((void**)&uv, g_uv);
    cudaGetSymbolAddress((void**)&Bh, g_Bh);
    cudaGetSymbolAddress((void**)&Bl, g_Bl);
    cudaGetSymbolAddress((void**)&s,  g_s);
    cudaGetSymbolAddress((void**)&t,  g_t);
    cudaGetSymbolAddress((void**)&deg, g_deg);
    cudaGetSymbolAddress((void**)&off, g_off);
    cudaGetSymbolAddress((void**)&cursor, g_cursor);
    cudaGetSymbolAddress((void**)&csrc, g_csrc);

    const int dynSmem = 2 * STG_STAGE;   // 81920 bytes
    cudaFuncSetAttribute(mma_gemm_kernel,
                         cudaFuncAttributeMaxDynamicSharedMemorySize, dynSmem);

    const int TPB = 256;
    dim3 gN((NN + TPB - 1) / TPB);
    dim3 gE((EE + TPB - 1) / TPB);
    dim3 gWarpN((NN * 32 + TPB - 1) / TPB);
    dim3 gWarpE((EE * 32 + TPB - 1) / TPB);
    const int MB = (NN + GBM - 1) / GBM;   // 391

    // launch order arranged so GEMM1 is the 6th launch (ncu -s 5 -c 1)
    pack_b_kernel<<<(256 * 2048 + TPB - 1) / TPB, TPB>>>(W1, Bh, Bl, 2048, 256);  // 1
    init_deg_kernel<<<gN, TPB>>>(deg, NN);                                        // 2
    count_kernel<<<gE, TPB>>>(edst, deg, EE);                                     // 3
    scan_kernel<<<1, 1024>>>(deg, off, NN);                                       // 4
    selfloop_kernel<<<gN, TPB>>>(off, cursor, csrc, NN);                          // 5
    mma_gemm_kernel<<<dim3(MB, 2), 256, dynSmem>>>(x, Bh, Bl, fA, NN, 2048, 256); // 6 (profiled)
    scatter_kernel<<<gE, TPB>>>(esrc, edst, cursor, csrc, EE);                    // 7

    node_dots_kernel<<<gWarpN, TPB>>>(fA, a_src1, a_dst1, s, t, NN);
    gat_agg_kernel<<<gWarpN, TPB>>>(fA, s, t, off, csrc, b1, fB, NN);

    // ---- layer 2 ----
    pack_b_kernel<<<(256 * 256 + TPB - 1) / TPB, TPB>>>(W2, Bh, Bl, 256, 256);
    mma_gemm_kernel<<<dim3(MB, 2), 256, dynSmem>>>(fB, Bh, Bl, fC, NN, 256, 256);
    node_dots_kernel<<<gWarpN, TPB>>>(fC, a_src2, a_dst2, s, t, NN);
    gat_agg_kernel<<<gWarpN, TPB>>>(fC, s, t, off, csrc, b2, fD, NN);

    // ---- edge predictor: [u | v] = h2 @ [Wp1_top | Wp1_bot] (N=512) ----
    pack_b_kernel<<<(256 * 256 + TPB - 1) / TPB, TPB>>>(Wp1, Bh, Bl, 256, 256);
    pack_b_kernel<<<(256 * 256 + TPB - 1) / TPB, TPB>>>(Wp1 + 256 * 256,
                                                        Bh + 256 * 256, Bl + 256 * 256,
                                                        256, 256);
    mma_gemm_kernel<<<dim3(MB, 4), 256, dynSmem>>>(fD, Bh, Bl, uv, NN, 256, 512);
    edge_pred_kernel<<<gWarpE, TPB>>>(uv, esrc, edst, bp1, wp2, bp2, out, EE);
}